// round 15
// baseline (speedup 1.0000x reference)
#include <cuda_runtime.h>

// Problem constants
#define BB   256   // batch
#define NN   196   // tokens
#define DD   768   // dim
#define PP   32    // pool size
#define TOPK 5
#define MM   128   // PP*4 rows of patch-embed GEMM
#define KDIM 768   // 3*16*16

// Output layout (flattened tuple, float32):
//   prompted_embedding (256,216,768) | reduce_sim (1) | similarity (256,32) | idx (256,5)
#define O_RS  (42467328ll)
#define O_SIM (O_RS + 1)          // odd float offset -> 4B-aligned only; scalar stores
#define O_IDX (O_SIM + (long long)BB * PP)

#define N_GEMM      32            // 32x96 tiles: 4 x 8 covers 128x768
#define N_PRODUCERS 33            // 32 GEMM + 1 pnorm
// grid = 33 + 256 = 289 <= 296 wave-1 slots (2 blocks/SM) -> no stragglers

// Scratch (static device globals); float4-touched => align 16
__device__ __align__(16) float g_pembed[MM * DD];   // patch-embed result (128,768)
__device__ __align__(16) float g_pnorm[PP * DD];    // l2-normalized prompt_key
__device__ __align__(16) float g_rs[BB];            // per-batch top-5 sim sums
__device__ int   g_ready;             // producer completion counter
__device__ int   g_counter;           // tail completion counter

// ---------------------------------------------------------------------------
// Single fused kernel — R5 topology with a 289-block grid (all wave-1):
//   blocks [0,32):   patch-embed GEMM (32x96 tiles) -> g_pembed, signal
//   block  32:       prompt_key L2 normalize -> g_pnorm, signal
//   blocks [33,289): copy x_embed -> out rows[20,216) (192 thr, 7-deep float4
//                    batches), mean in SMEM, then sim+top5+gather for batch b.
// All 289 blocks co-resident; producers wait on nothing => spin is safe.
// ---------------------------------------------------------------------------
__global__ void __launch_bounds__(256) fused_kernel(
    const float* __restrict__ x,       // (256,196,768)
    const float* __restrict__ prompt,  // (32,3,32,32)
    const float* __restrict__ pkey,    // (32,768)
    const float* __restrict__ w,       // (768,3,16,16) == (768,768) row-major
    const float* __restrict__ bias,    // (768)
    float* __restrict__ out)
{
    const int bx = blockIdx.x;
    const int t  = threadIdx.x;
    const int warp = t >> 5, lane = t & 31;
    const unsigned FULL = 0xffffffffu;

    if (bx < N_GEMM) {
        // ---- patch-embed GEMM: g_pembed[m,d] = sum_k A[m,k]*W[d,k] + bias[d]
        // 32x96 output tile; 256 threads -> 2x6 outputs each (16x16 thread grid)
        __shared__ __align__(16) float As[32][33];
        __shared__ __align__(16) float Ws[96][33];
        const int m0 = (bx >> 3) * 32;     // 4 row-tiles
        const int n0 = (bx & 7) * 96;      // 8 col-tiles
        const int tx = t & 15;             // 6 output cols each
        const int ty = t >> 4;             // 2 output rows each
        float acc[2][6] = {{0,0,0,0,0,0},{0,0,0,0,0,0}};

        const float4* w4 = reinterpret_cast<const float4*>(w);

        for (int k0 = 0; k0 < KDIM; k0 += 32) {
            // A tile: 32 m x 32 k from strided conv-patch layout
            #pragma unroll
            for (int s = 0; s < 4; s++) {
                int e  = s * 256 + t;
                int mm = e >> 5;
                int kk = e & 31;
                int m  = m0 + mm;
                int p  = m >> 2;
                int l  = m & 3;
                int py = l >> 1, px = l & 1;
                int k  = k0 + kk;
                int c  = k >> 8;
                int rem = k & 255;
                int ii = rem >> 4, jj = rem & 15;
                As[mm][kk] = prompt[((size_t)(p * 3 + c) * 32 + py * 16 + ii) * 32
                                    + px * 16 + jj];
            }
            // W tile: 96 d x 32 k, vectorized (768 float4, 3 per thread)
            #pragma unroll
            for (int s = 0; s < 3; s++) {
                int v  = s * 256 + t;        // 0..767
                int dd = v >> 3;             // 0..95
                int kv = v & 7;
                float4 f = w4[(size_t)(n0 + dd) * 192 + (k0 >> 2) + kv];
                Ws[dd][kv * 4 + 0] = f.x;
                Ws[dd][kv * 4 + 1] = f.y;
                Ws[dd][kv * 4 + 2] = f.z;
                Ws[dd][kv * 4 + 3] = f.w;
            }
            __syncthreads();
            #pragma unroll
            for (int kk = 0; kk < 32; kk++) {
                float a0 = As[ty * 2 + 0][kk];
                float a1 = As[ty * 2 + 1][kk];
                #pragma unroll
                for (int j = 0; j < 6; j++) {
                    float wv = Ws[tx * 6 + j][kk];
                    acc[0][j] += a0 * wv;
                    acc[1][j] += a1 * wv;
                }
            }
            __syncthreads();
        }
        #pragma unroll
        for (int r = 0; r < 2; r++) {
            #pragma unroll
            for (int j = 0; j < 6; j++) {
                int m = m0 + ty * 2 + r;
                int d = n0 + tx * 6 + j;
                g_pembed[m * DD + d] = acc[r][j] + bias[d];
            }
        }
        __syncthreads();
        __threadfence();
        if (t == 0) atomicAdd(&g_ready, 1);

    } else if (bx == N_GEMM) {
        // ---- prompt_key L2 normalize: 8 warps x 4 rows
        for (int p = warp; p < PP; p += 8) {
            const float* row = pkey + (size_t)p * DD;
            float sq = 0.f;
            for (int k = lane; k < DD; k += 32) { float v = row[k]; sq += v * v; }
            #pragma unroll
            for (int o = 16; o; o >>= 1) sq += __shfl_xor_sync(FULL, sq, o);
            float rs = rsqrtf(fmaxf(sq, 1e-12f));
            for (int k = lane; k < DD; k += 32) g_pnorm[p * DD + k] = row[k] * rs;
        }
        __syncthreads();
        __threadfence();
        if (t == 0) atomicAdd(&g_ready, 1);

    } else {
        // ================= copy + fused per-batch tail (R5-exact) ============
        __shared__ __align__(16) float sx[DD];
        __shared__ float s_red[8];
        __shared__ float s_sim[PP];
        __shared__ int   s_idx[TOPK];
        __shared__ int   s_last;

        const int b = bx - N_PRODUCERS;

        // ---- copy x_embed rows -> out rows [20,216) + mean into SMEM
        if (t < 192) {
            const float4* src = reinterpret_cast<const float4*>(x)
                                + (size_t)b * NN * 192 + t;
            float4* dst = reinterpret_cast<float4*>(out)
                          + ((size_t)b * 216 + 20) * 192 + t;
            float4 acc = make_float4(0.f, 0.f, 0.f, 0.f);
            #pragma unroll 1
            for (int n = 0; n < NN; n += 7) {     // 196 = 28 * 7, deep MLP
                float4 v[7];
                #pragma unroll
                for (int u = 0; u < 7; u++) v[u] = __ldcs(&src[(size_t)(n + u) * 192]);
                #pragma unroll
                for (int u = 0; u < 7; u++) {
                    __stcs(&dst[(size_t)(n + u) * 192], v[u]);
                    acc.x += v[u].x; acc.y += v[u].y;
                    acc.z += v[u].z; acc.w += v[u].w;
                }
            }
            const float inv = 1.0f / 196.0f;
            acc.x *= inv; acc.y *= inv; acc.z *= inv; acc.w *= inv;
            reinterpret_cast<float4*>(sx)[t] = acc;
        }

        // ---- wait for GEMM + pnorm producers (all co-resident: safe)
        if (t == 0) {
            while (atomicAdd(&g_ready, 0) < N_PRODUCERS) { }
        }
        __syncthreads();
        __threadfence();

        // ---- squared norm of mean (from SMEM)
        float sq = 0.f;
        #pragma unroll
        for (int i = 0; i < 3; i++) {
            float v = sx[t + i * 256];
            sq += v * v;
        }
        #pragma unroll
        for (int o = 16; o; o >>= 1) sq += __shfl_xor_sync(FULL, sq, o);
        if (lane == 0) s_red[warp] = sq;
        __syncthreads();
        float rv = (lane < 8) ? s_red[lane] : 0.f;
        #pragma unroll
        for (int o = 4; o; o >>= 1) rv += __shfl_xor_sync(FULL, rv, o);
        const float rs = rsqrtf(fmaxf(__shfl_sync(FULL, rv, 0), 1e-12f));

        // ---- similarity: warp w owns pool rows 4w..4w+3, interleaved dots
        {
            const float* __restrict__ pn0 = g_pnorm + (size_t)(warp * 4 + 0) * DD;
            const float* __restrict__ pn1 = g_pnorm + (size_t)(warp * 4 + 1) * DD;
            const float* __restrict__ pn2 = g_pnorm + (size_t)(warp * 4 + 2) * DD;
            const float* __restrict__ pn3 = g_pnorm + (size_t)(warp * 4 + 3) * DD;
            float d0 = 0.f, d1 = 0.f, d2 = 0.f, d3 = 0.f;
            #pragma unroll
            for (int i = 0; i < DD / 32; i++) {      // fully unrolled -> MLP high
                int k = lane + i * 32;
                float xv = sx[k];
                d0 += xv * __ldg(pn0 + k);
                d1 += xv * __ldg(pn1 + k);
                d2 += xv * __ldg(pn2 + k);
                d3 += xv * __ldg(pn3 + k);
            }
            #pragma unroll
            for (int o = 16; o; o >>= 1) {
                d0 += __shfl_xor_sync(FULL, d0, o);
                d1 += __shfl_xor_sync(FULL, d1, o);
                d2 += __shfl_xor_sync(FULL, d2, o);
                d3 += __shfl_xor_sync(FULL, d3, o);
            }
            if (lane == 0) {
                int p = warp * 4;
                float v0 = d0 * rs, v1 = d1 * rs, v2 = d2 * rs, v3 = d3 * rs;
                s_sim[p + 0] = v0; s_sim[p + 1] = v1;
                s_sim[p + 2] = v2; s_sim[p + 3] = v3;
                float* so = out + O_SIM + (size_t)b * PP + p;   // 4B-aligned only
                so[0] = v0; so[1] = v1; so[2] = v2; so[3] = v3;
            }
        }
        __syncthreads();

        // ---- top-5 (warp 0): iterative argmax, lower index wins ties
        if (warp == 0) {
            float v = s_sim[lane];
            unsigned sel = 0u;
            float lsum = 0.f;
            #pragma unroll
            for (int k = 0; k < TOPK; k++) {
                float bv = ((sel >> lane) & 1u) ? -__int_as_float(0x7f800000) : v;
                int   bi = lane;
                #pragma unroll
                for (int o = 16; o; o >>= 1) {
                    float ov = __shfl_xor_sync(FULL, bv, o);
                    int   oi = __shfl_xor_sync(FULL, bi, o);
                    if (ov > bv || (ov == bv && oi < bi)) { bv = ov; bi = oi; }
                }
                sel |= 1u << bi;
                if (lane == 0) {
                    s_idx[k] = bi;
                    out[O_IDX + (size_t)b * TOPK + k] = (float)bi;
                    lsum += bv;
                }
            }
            if (lane == 0) g_rs[b] = lsum;
        }
        __syncthreads();

        // ---- gather 20 rows (5 prompts x 4 patches) into out rows [0,20)
        const float4* pe4 = reinterpret_cast<const float4*>(g_pembed);
        float4* ob4 = reinterpret_cast<float4*>(out) + (size_t)b * 216 * 192;
        #pragma unroll
        for (int e = t; e < 20 * 192; e += 256) {
            int j = e / 192;          // output row 0..19
            int c = e - j * 192;      // float4 column
            int i = s_idx[j >> 2];    // selected prompt
            int row = i * 4 + (j & 3);
            ob4[(size_t)j * 192 + c] = __ldg(pe4 + (size_t)row * 192 + c);
        }

        // ---- deterministic reduce_sim: last arriving block sums in order
        if (t == 0) {
            __threadfence();
            int old = atomicAdd(&g_counter, 1);
            s_last = (old == BB - 1);
        }
        __syncthreads();
        if (s_last) {
            __threadfence();
            float v = g_rs[t];
            #pragma unroll
            for (int o = 16; o; o >>= 1) v += __shfl_xor_sync(FULL, v, o);
            if (lane == 0) s_red[warp] = v;
            __syncthreads();
            if (t == 0) {
                float tot = 0.f;
                #pragma unroll
                for (int wv = 0; wv < 8; wv++) tot += s_red[wv];
                out[O_RS] = tot / (float)BB;
                g_counter = 0;                   // reset for next graph replay
                g_ready   = 0;
            }
        }
    }
}

// ---------------------------------------------------------------------------
extern "C" void kernel_launch(void* const* d_in, const int* in_sizes, int n_in,
                              void* d_out, int out_size)
{
    const float* x      = (const float*)d_in[0];  // x_embed  (256,196,768)
    const float* prompt = (const float*)d_in[1];  // prompt   (32,3,32,32)
    const float* pkey   = (const float*)d_in[2];  // prompt_key (32,768)
    const float* w      = (const float*)d_in[3];  // conv_w   (768,3,16,16)
    const float* bias   = (const float*)d_in[4];  // conv_b   (768)
    float* out = (float*)d_out;

    fused_kernel<<<N_PRODUCERS + BB, 256>>>(x, prompt, pkey, w, bias, out);
}

// round 16
// speedup vs baseline: 1.1616x; 1.1616x over previous
#include <cuda_runtime.h>

// Problem constants
#define BB   256   // batch
#define NN   196   // tokens
#define DD   768   // dim
#define PP   32    // pool size
#define TOPK 5
#define MM   128   // PP*4 rows of patch-embed GEMM
#define KDIM 768   // 3*16*16

// Output layout (flattened tuple, float32):
//   prompted_embedding (256,216,768) | reduce_sim (1) | similarity (256,32) | idx (256,5)
#define O_RS  (42467328ll)
#define O_SIM (O_RS + 1)          // odd float offset -> 4B-aligned only; scalar stores
#define O_IDX (O_SIM + (long long)BB * PP)

#define N_PRODUCERS 49            // 48 GEMM blocks + 1 pnorm block

// Scratch (static device globals — no allocation allowed)
__device__ float g_pembed[MM * DD];   // patch-embed result (128,768)
__device__ float g_pnorm[PP * DD];    // l2-normalized prompt_key
__device__ float g_rs[BB];            // per-batch top-5 sim sums
__device__ int   g_ready;             // producer completion counter
__device__ int   g_counter;           // tail completion counter

// ---------------------------------------------------------------------------
// Single fused kernel, three block roles:
//   blocks [0,48):   patch-embed GEMM -> g_pembed, then signal g_ready
//   block  48:       prompt_key L2 normalize -> g_pnorm, then signal g_ready
//   blocks [49,305): copy x_embed -> out rows[20,216), mean kept in SMEM,
//                    then spin on g_ready and run sim+top5+gather for batch b.
// All 305 blocks are co-resident (<=12.7KB smem, 256 thr), so the spin is safe.
// ---------------------------------------------------------------------------
__global__ __launch_bounds__(256) void fused_kernel(
    const float* __restrict__ x,       // (256,196,768)
    const float* __restrict__ prompt,  // (32,3,32,32)
    const float* __restrict__ pkey,    // (32,768)
    const float* __restrict__ w,       // (768,3,16,16) == (768,768) row-major
    const float* __restrict__ bias,    // (768)
    float* __restrict__ out)
{
    const int bx = blockIdx.x;
    const int t  = threadIdx.x;
    const int warp = t >> 5, lane = t & 31;
    const unsigned FULL = 0xffffffffu;

    if (bx < 48) {
        // ---- patch-embed GEMM: g_pembed[m,d] = sum_k A[m,k]*W[d,k] + bias[d]
        __shared__ float As[32][33];
        __shared__ float Ws[64][33];
        const int m0 = (bx / 12) * 32;
        const int n0 = (bx % 12) * 64;
        const int tx = t & 15;    // 4 output cols each
        const int ty = t >> 4;    // 2 output rows each
        float acc[2][4] = {{0.f,0.f,0.f,0.f},{0.f,0.f,0.f,0.f}};

        const float4* w4 = reinterpret_cast<const float4*>(w);

        for (int k0 = 0; k0 < KDIM; k0 += 32) {
            #pragma unroll
            for (int s = 0; s < 4; s++) {
                int e  = s * 256 + t;
                int mm = e >> 5;
                int kk = e & 31;
                int m  = m0 + mm;
                int p  = m >> 2;
                int l  = m & 3;
                int py = l >> 1, px = l & 1;
                int k  = k0 + kk;
                int c  = k >> 8;
                int rem = k & 255;
                int ii = rem >> 4, jj = rem & 15;
                As[mm][kk] = prompt[((size_t)(p * 3 + c) * 32 + py * 16 + ii) * 32
                                    + px * 16 + jj];
            }
            #pragma unroll
            for (int s = 0; s < 2; s++) {
                int v  = s * 256 + t;        // 0..511
                int dd = v >> 3;             // 0..63
                int kv = v & 7;
                float4 f = w4[(size_t)(n0 + dd) * 192 + (k0 >> 2) + kv];
                Ws[dd][kv * 4 + 0] = f.x;
                Ws[dd][kv * 4 + 1] = f.y;
                Ws[dd][kv * 4 + 2] = f.z;
                Ws[dd][kv * 4 + 3] = f.w;
            }
            __syncthreads();
            #pragma unroll
            for (int kk = 0; kk < 32; kk++) {
                float a0 = As[ty * 2 + 0][kk];
                float a1 = As[ty * 2 + 1][kk];
                #pragma unroll
                for (int j = 0; j < 4; j++) {
                    float wv = Ws[tx * 4 + j][kk];
                    acc[0][j] += a0 * wv;
                    acc[1][j] += a1 * wv;
                }
            }
            __syncthreads();
        }
        #pragma unroll
        for (int r = 0; r < 2; r++) {
            #pragma unroll
            for (int j = 0; j < 4; j++) {
                int m = m0 + ty * 2 + r;
                int d = n0 + tx * 4 + j;
                g_pembed[m * DD + d] = acc[r][j] + bias[d];
            }
        }
        // signal completion
        __syncthreads();
        __threadfence();
        if (t == 0) atomicAdd(&g_ready, 1);

    } else if (bx == 48) {
        // ---- prompt_key L2 normalize: 8 warps x 4 rows
        for (int p = warp; p < PP; p += 8) {
            const float* row = pkey + (size_t)p * DD;
            float sq = 0.f;
            for (int k = lane; k < DD; k += 32) { float v = row[k]; sq += v * v; }
            #pragma unroll
            for (int o = 16; o; o >>= 1) sq += __shfl_xor_sync(FULL, sq, o);
            float rs = rsqrtf(fmaxf(sq, 1e-12f));
            for (int k = lane; k < DD; k += 32) g_pnorm[p * DD + k] = row[k] * rs;
        }
        __syncthreads();
        __threadfence();
        if (t == 0) atomicAdd(&g_ready, 1);

    } else {
        // ================= copy + fused per-batch tail =================
        __shared__ float sx[DD];
        __shared__ float s_red[8];
        __shared__ float s_sim[PP];
        __shared__ int   s_idx[TOPK];
        __shared__ int   s_last;

        const int b = bx - N_PRODUCERS;

        // ---- copy x_embed rows -> out rows [20,216) + mean into SMEM
        if (t < 192) {
            const float4* src = reinterpret_cast<const float4*>(x)
                                + (size_t)b * NN * 192 + t;
            float4* dst = reinterpret_cast<float4*>(out)
                          + ((size_t)b * 216 + 20) * 192 + t;
            float4 acc = make_float4(0.f, 0.f, 0.f, 0.f);
            #pragma unroll 1
            for (int n = 0; n < NN; n += 7) {     // 196 = 28 * 7, deep MLP
                float4 v[7];
                #pragma unroll
                for (int u = 0; u < 7; u++) v[u] = __ldcs(&src[(size_t)(n + u) * 192]);
                #pragma unroll
                for (int u = 0; u < 7; u++) {
                    __stcs(&dst[(size_t)(n + u) * 192], v[u]);
                    acc.x += v[u].x; acc.y += v[u].y;
                    acc.z += v[u].z; acc.w += v[u].w;
                }
            }
            const float inv = 1.0f / 196.0f;
            acc.x *= inv; acc.y *= inv; acc.z *= inv; acc.w *= inv;
            reinterpret_cast<float4*>(sx)[t] = acc;
        }

        // ---- wait for GEMM + pnorm producers (all blocks co-resident: safe)
        if (t == 0) {
            while (atomicAdd(&g_ready, 0) < N_PRODUCERS) { }
        }
        __syncthreads();
        __threadfence();

        // ---- squared norm of mean (from SMEM)
        float sq = 0.f;
        #pragma unroll
        for (int i = 0; i < 3; i++) {
            int k = t + i * 256;
            float v = sx[k];
            sq += v * v;
        }
        #pragma unroll
        for (int o = 16; o; o >>= 1) sq += __shfl_xor_sync(FULL, sq, o);
        if (lane == 0) s_red[warp] = sq;
        __syncthreads();
        float rv = (lane < 8) ? s_red[lane] : 0.f;
        #pragma unroll
        for (int o = 4; o; o >>= 1) rv += __shfl_xor_sync(FULL, rv, o);
        const float rs = rsqrtf(fmaxf(__shfl_sync(FULL, rv, 0), 1e-12f));

        // ---- similarity: warp w owns pool rows 4w..4w+3, interleaved dots
        {
            const float* __restrict__ pn0 = g_pnorm + (size_t)(warp * 4 + 0) * DD;
            const float* __restrict__ pn1 = g_pnorm + (size_t)(warp * 4 + 1) * DD;
            const float* __restrict__ pn2 = g_pnorm + (size_t)(warp * 4 + 2) * DD;
            const float* __restrict__ pn3 = g_pnorm + (size_t)(warp * 4 + 3) * DD;
            float d0 = 0.f, d1 = 0.f, d2 = 0.f, d3 = 0.f;
            #pragma unroll
            for (int i = 0; i < DD / 32; i++) {      // fully unrolled -> MLP high
                int k = lane + i * 32;
                float xv = sx[k];
                d0 += xv * __ldg(pn0 + k);
                d1 += xv * __ldg(pn1 + k);
                d2 += xv * __ldg(pn2 + k);
                d3 += xv * __ldg(pn3 + k);
            }
            #pragma unroll
            for (int o = 16; o; o >>= 1) {
                d0 += __shfl_xor_sync(FULL, d0, o);
                d1 += __shfl_xor_sync(FULL, d1, o);
                d2 += __shfl_xor_sync(FULL, d2, o);
                d3 += __shfl_xor_sync(FULL, d3, o);
            }
            if (lane == 0) {
                int p = warp * 4;
                float v0 = d0 * rs, v1 = d1 * rs, v2 = d2 * rs, v3 = d3 * rs;
                s_sim[p + 0] = v0; s_sim[p + 1] = v1;
                s_sim[p + 2] = v2; s_sim[p + 3] = v3;
                float* so = out + O_SIM + (size_t)b * PP + p;   // 4B-aligned only
                so[0] = v0; so[1] = v1; so[2] = v2; so[3] = v3;
            }
        }
        __syncthreads();

        // ---- top-5 (warp 0): iterative argmax, lower index wins ties
        if (warp == 0) {
            float v = s_sim[lane];
            unsigned sel = 0u;
            float lsum = 0.f;
            #pragma unroll
            for (int k = 0; k < TOPK; k++) {
                float bv = ((sel >> lane) & 1u) ? -__int_as_float(0x7f800000) : v;
                int   bi = lane;
                #pragma unroll
                for (int o = 16; o; o >>= 1) {
                    float ov = __shfl_xor_sync(FULL, bv, o);
                    int   oi = __shfl_xor_sync(FULL, bi, o);
                    if (ov > bv || (ov == bv && oi < bi)) { bv = ov; bi = oi; }
                }
                sel |= 1u << bi;
                if (lane == 0) {
                    s_idx[k] = bi;
                    out[O_IDX + (size_t)b * TOPK + k] = (float)bi;
                    lsum += bv;
                }
            }
            if (lane == 0) g_rs[b] = lsum;
        }
        __syncthreads();

        // ---- gather 20 rows (5 prompts x 4 patches) into out rows [0,20)
        const float4* pe4 = reinterpret_cast<const float4*>(g_pembed);
        float4* ob4 = reinterpret_cast<float4*>(out) + (size_t)b * 216 * 192;
        #pragma unroll
        for (int e = t; e < 20 * 192; e += 256) {
            int j = e / 192;          // output row 0..19
            int c = e - j * 192;      // float4 column
            int i = s_idx[j >> 2];    // selected prompt
            int row = i * 4 + (j & 3);
            ob4[(size_t)j * 192 + c] = __ldg(pe4 + (size_t)row * 192 + c);
        }

        // ---- deterministic reduce_sim: last arriving block sums in order
        if (t == 0) {
            __threadfence();
            int old = atomicAdd(&g_counter, 1);
            s_last = (old == BB - 1);
        }
        __syncthreads();
        if (s_last) {
            __threadfence();
            float v = g_rs[t];
            #pragma unroll
            for (int o = 16; o; o >>= 1) v += __shfl_xor_sync(FULL, v, o);
            if (lane == 0) s_red[warp] = v;
            __syncthreads();
            if (t == 0) {
                float tot = 0.f;
                #pragma unroll
                for (int wv = 0; wv < 8; wv++) tot += s_red[wv];
                out[O_RS] = tot / (float)BB;
                g_counter = 0;                   // reset for next graph replay
                g_ready   = 0;
            }
        }
    }
}

// ---------------------------------------------------------------------------
extern "C" void kernel_launch(void* const* d_in, const int* in_sizes, int n_in,
                              void* d_out, int out_size)
{
    const float* x      = (const float*)d_in[0];  // x_embed  (256,196,768)
    const float* prompt = (const float*)d_in[1];  // prompt   (32,3,32,32)
    const float* pkey   = (const float*)d_in[2];  // prompt_key (32,768)
    const float* w      = (const float*)d_in[3];  // conv_w   (768,3,16,16)
    const float* bias   = (const float*)d_in[4];  // conv_b   (768)
    float* out = (float*)d_out;

    fused_kernel<<<N_PRODUCERS + BB, 256>>>(x, prompt, pkey, w, bias, out);
}

// round 17
// speedup vs baseline: 1.1743x; 1.0109x over previous
#include <cuda_runtime.h>

// Problem constants
#define BB   256   // batch
#define NN   196   // tokens
#define DD   768   // dim
#define PP   32    // pool size
#define TOPK 5
#define MM   128   // PP*4 rows of patch-embed GEMM
#define KDIM 768   // 3*16*16

// Output layout (flattened tuple, float32):
//   prompted_embedding (256,216,768) | reduce_sim (1) | similarity (256,32) | idx (256,5)
#define O_RS  (42467328ll)
#define O_SIM (O_RS + 1)          // odd float offset -> 4B-aligned only; scalar stores
#define O_IDX (O_SIM + (long long)BB * PP)

#define N_PRODUCERS 49            // 48 GEMM blocks + 1 pnorm block

// Scratch (static device globals — no allocation allowed)
__device__ float g_pembed[MM * DD];   // patch-embed result (128,768)
__device__ float g_pnorm[PP * DD];    // l2-normalized prompt_key
__device__ float g_rs[BB];            // per-batch top-5 sim sums
__device__ int   g_ready;             // producer completion counter
__device__ int   g_counter;           // tail completion counter

// ---------------------------------------------------------------------------
// Single fused kernel (champion R5/R16 topology). ONE delta: the copy loop is
// software-pipelined — batch n+1's 7 loads issue BEFORE batch n's 7 stores,
// so the read stream never drains at a batch boundary (less HBM rd/wr
// turnaround). Load depth stays 7 (the proven optimum).
//   blocks [0,48):   patch-embed GEMM -> g_pembed, then signal g_ready
//   block  48:       prompt_key L2 normalize -> g_pnorm, then signal g_ready
//   blocks [49,305): copy x_embed -> out rows[20,216), mean kept in SMEM,
//                    then spin on g_ready and run sim+top5+gather for batch b.
// All 305 blocks are co-resident, so the spin is safe.
// ---------------------------------------------------------------------------
__global__ __launch_bounds__(256) void fused_kernel(
    const float* __restrict__ x,       // (256,196,768)
    const float* __restrict__ prompt,  // (32,3,32,32)
    const float* __restrict__ pkey,    // (32,768)
    const float* __restrict__ w,       // (768,3,16,16) == (768,768) row-major
    const float* __restrict__ bias,    // (768)
    float* __restrict__ out)
{
    const int bx = blockIdx.x;
    const int t  = threadIdx.x;
    const int warp = t >> 5, lane = t & 31;
    const unsigned FULL = 0xffffffffu;

    if (bx < 48) {
        // ---- patch-embed GEMM: g_pembed[m,d] = sum_k A[m,k]*W[d,k] + bias[d]
        __shared__ float As[32][33];
        __shared__ float Ws[64][33];
        const int m0 = (bx / 12) * 32;
        const int n0 = (bx % 12) * 64;
        const int tx = t & 15;    // 4 output cols each
        const int ty = t >> 4;    // 2 output rows each
        float acc[2][4] = {{0.f,0.f,0.f,0.f},{0.f,0.f,0.f,0.f}};

        const float4* w4 = reinterpret_cast<const float4*>(w);

        for (int k0 = 0; k0 < KDIM; k0 += 32) {
            #pragma unroll
            for (int s = 0; s < 4; s++) {
                int e  = s * 256 + t;
                int mm = e >> 5;
                int kk = e & 31;
                int m  = m0 + mm;
                int p  = m >> 2;
                int l  = m & 3;
                int py = l >> 1, px = l & 1;
                int k  = k0 + kk;
                int c  = k >> 8;
                int rem = k & 255;
                int ii = rem >> 4, jj = rem & 15;
                As[mm][kk] = prompt[((size_t)(p * 3 + c) * 32 + py * 16 + ii) * 32
                                    + px * 16 + jj];
            }
            #pragma unroll
            for (int s = 0; s < 2; s++) {
                int v  = s * 256 + t;        // 0..511
                int dd = v >> 3;             // 0..63
                int kv = v & 7;
                float4 f = w4[(size_t)(n0 + dd) * 192 + (k0 >> 2) + kv];
                Ws[dd][kv * 4 + 0] = f.x;
                Ws[dd][kv * 4 + 1] = f.y;
                Ws[dd][kv * 4 + 2] = f.z;
                Ws[dd][kv * 4 + 3] = f.w;
            }
            __syncthreads();
            #pragma unroll
            for (int kk = 0; kk < 32; kk++) {
                float a0 = As[ty * 2 + 0][kk];
                float a1 = As[ty * 2 + 1][kk];
                #pragma unroll
                for (int j = 0; j < 4; j++) {
                    float wv = Ws[tx * 4 + j][kk];
                    acc[0][j] += a0 * wv;
                    acc[1][j] += a1 * wv;
                }
            }
            __syncthreads();
        }
        #pragma unroll
        for (int r = 0; r < 2; r++) {
            #pragma unroll
            for (int j = 0; j < 4; j++) {
                int m = m0 + ty * 2 + r;
                int d = n0 + tx * 4 + j;
                g_pembed[m * DD + d] = acc[r][j] + bias[d];
            }
        }
        __syncthreads();
        __threadfence();
        if (t == 0) atomicAdd(&g_ready, 1);

    } else if (bx == 48) {
        // ---- prompt_key L2 normalize: 8 warps x 4 rows
        for (int p = warp; p < PP; p += 8) {
            const float* row = pkey + (size_t)p * DD;
            float sq = 0.f;
            for (int k = lane; k < DD; k += 32) { float v = row[k]; sq += v * v; }
            #pragma unroll
            for (int o = 16; o; o >>= 1) sq += __shfl_xor_sync(FULL, sq, o);
            float rs = rsqrtf(fmaxf(sq, 1e-12f));
            for (int k = lane; k < DD; k += 32) g_pnorm[p * DD + k] = row[k] * rs;
        }
        __syncthreads();
        __threadfence();
        if (t == 0) atomicAdd(&g_ready, 1);

    } else {
        // ================= copy + fused per-batch tail =================
        __shared__ float sx[DD];
        __shared__ float s_red[8];
        __shared__ float s_sim[PP];
        __shared__ int   s_idx[TOPK];
        __shared__ int   s_last;

        const int b = bx - N_PRODUCERS;

        // ---- copy x_embed rows -> out rows [20,216) + mean into SMEM
        // Software-pipelined: prefetch batch n+1's loads before batch n's
        // stores. Same 7-deep load batches, same summation order (bit-exact).
        if (t < 192) {
            const float4* src = reinterpret_cast<const float4*>(x)
                                + (size_t)b * NN * 192 + t;
            float4* dst = reinterpret_cast<float4*>(out)
                          + ((size_t)b * 216 + 20) * 192 + t;
            float4 acc = make_float4(0.f, 0.f, 0.f, 0.f);
            float4 cur[7], nxt[7];
            #pragma unroll
            for (int u = 0; u < 7; u++) cur[u] = __ldcs(&src[(size_t)u * 192]);
            #pragma unroll 1
            for (int n = 0; n < NN - 7; n += 7) {     // 27 steady iterations
                #pragma unroll
                for (int u = 0; u < 7; u++)
                    nxt[u] = __ldcs(&src[(size_t)(n + 7 + u) * 192]);
                #pragma unroll
                for (int u = 0; u < 7; u++) {
                    __stcs(&dst[(size_t)(n + u) * 192], cur[u]);
                    acc.x += cur[u].x; acc.y += cur[u].y;
                    acc.z += cur[u].z; acc.w += cur[u].w;
                }
                #pragma unroll
                for (int u = 0; u < 7; u++) cur[u] = nxt[u];
            }
            #pragma unroll
            for (int u = 0; u < 7; u++) {            // epilogue batch
                __stcs(&dst[(size_t)(NN - 7 + u) * 192], cur[u]);
                acc.x += cur[u].x; acc.y += cur[u].y;
                acc.z += cur[u].z; acc.w += cur[u].w;
            }
            const float inv = 1.0f / 196.0f;
            acc.x *= inv; acc.y *= inv; acc.z *= inv; acc.w *= inv;
            reinterpret_cast<float4*>(sx)[t] = acc;
        }

        // ---- wait for GEMM + pnorm producers (all blocks co-resident: safe)
        if (t == 0) {
            while (atomicAdd(&g_ready, 0) < N_PRODUCERS) { }
        }
        __syncthreads();
        __threadfence();

        // ---- squared norm of mean (from SMEM)
        float sq = 0.f;
        #pragma unroll
        for (int i = 0; i < 3; i++) {
            int k = t + i * 256;
            float v = sx[k];
            sq += v * v;
        }
        #pragma unroll
        for (int o = 16; o; o >>= 1) sq += __shfl_xor_sync(FULL, sq, o);
        if (lane == 0) s_red[warp] = sq;
        __syncthreads();
        float rv = (lane < 8) ? s_red[lane] : 0.f;
        #pragma unroll
        for (int o = 4; o; o >>= 1) rv += __shfl_xor_sync(FULL, rv, o);
        const float rs = rsqrtf(fmaxf(__shfl_sync(FULL, rv, 0), 1e-12f));

        // ---- similarity: warp w owns pool rows 4w..4w+3, interleaved dots
        {
            const float* __restrict__ pn0 = g_pnorm + (size_t)(warp * 4 + 0) * DD;
            const float* __restrict__ pn1 = g_pnorm + (size_t)(warp * 4 + 1) * DD;
            const float* __restrict__ pn2 = g_pnorm + (size_t)(warp * 4 + 2) * DD;
            const float* __restrict__ pn3 = g_pnorm + (size_t)(warp * 4 + 3) * DD;
            float d0 = 0.f, d1 = 0.f, d2 = 0.f, d3 = 0.f;
            #pragma unroll
            for (int i = 0; i < DD / 32; i++) {      // fully unrolled -> MLP high
                int k = lane + i * 32;
                float xv = sx[k];
                d0 += xv * __ldg(pn0 + k);
                d1 += xv * __ldg(pn1 + k);
                d2 += xv * __ldg(pn2 + k);
                d3 += xv * __ldg(pn3 + k);
            }
            #pragma unroll
            for (int o = 16; o; o >>= 1) {
                d0 += __shfl_xor_sync(FULL, d0, o);
                d1 += __shfl_xor_sync(FULL, d1, o);
                d2 += __shfl_xor_sync(FULL, d2, o);
                d3 += __shfl_xor_sync(FULL, d3, o);
            }
            if (lane == 0) {
                int p = warp * 4;
                float v0 = d0 * rs, v1 = d1 * rs, v2 = d2 * rs, v3 = d3 * rs;
                s_sim[p + 0] = v0; s_sim[p + 1] = v1;
                s_sim[p + 2] = v2; s_sim[p + 3] = v3;
                float* so = out + O_SIM + (size_t)b * PP + p;   // 4B-aligned only
                so[0] = v0; so[1] = v1; so[2] = v2; so[3] = v3;
            }
        }
        __syncthreads();

        // ---- top-5 (warp 0): iterative argmax, lower index wins ties
        if (warp == 0) {
            float v = s_sim[lane];
            unsigned sel = 0u;
            float lsum = 0.f;
            #pragma unroll
            for (int k = 0; k < TOPK; k++) {
                float bv = ((sel >> lane) & 1u) ? -__int_as_float(0x7f800000) : v;
                int   bi = lane;
                #pragma unroll
                for (int o = 16; o; o >>= 1) {
                    float ov = __shfl_xor_sync(FULL, bv, o);
                    int   oi = __shfl_xor_sync(FULL, bi, o);
                    if (ov > bv || (ov == bv && oi < bi)) { bv = ov; bi = oi; }
                }
                sel |= 1u << bi;
                if (lane == 0) {
                    s_idx[k] = bi;
                    out[O_IDX + (size_t)b * TOPK + k] = (float)bi;
                    lsum += bv;
                }
            }
            if (lane == 0) g_rs[b] = lsum;
        }
        __syncthreads();

        // ---- gather 20 rows (5 prompts x 4 patches) into out rows [0,20)
        const float4* pe4 = reinterpret_cast<const float4*>(g_pembed);
        float4* ob4 = reinterpret_cast<float4*>(out) + (size_t)b * 216 * 192;
        #pragma unroll
        for (int e = t; e < 20 * 192; e += 256) {
            int j = e / 192;          // output row 0..19
            int c = e - j * 192;      // float4 column
            int i = s_idx[j >> 2];    // selected prompt
            int row = i * 4 + (j & 3);
            ob4[(size_t)j * 192 + c] = __ldg(pe4 + (size_t)row * 192 + c);
        }

        // ---- deterministic reduce_sim: last arriving block sums in order
        if (t == 0) {
            __threadfence();
            int old = atomicAdd(&g_counter, 1);
            s_last = (old == BB - 1);
        }
        __syncthreads();
        if (s_last) {
            __threadfence();
            float v = g_rs[t];
            #pragma unroll
            for (int o = 16; o; o >>= 1) v += __shfl_xor_sync(FULL, v, o);
            if (lane == 0) s_red[warp] = v;
            __syncthreads();
            if (t == 0) {
                float tot = 0.f;
                #pragma unroll
                for (int wv = 0; wv < 8; wv++) tot += s_red[wv];
                out[O_RS] = tot / (float)BB;
                g_counter = 0;                   // reset for next graph replay
                g_ready   = 0;
            }
        }
    }
}

// ---------------------------------------------------------------------------
extern "C" void kernel_launch(void* const* d_in, const int* in_sizes, int n_in,
                              void* d_out, int out_size)
{
    const float* x      = (const float*)d_in[0];  // x_embed  (256,196,768)
    const float* prompt = (const float*)d_in[1];  // prompt   (32,3,32,32)
    const float* pkey   = (const float*)d_in[2];  // prompt_key (32,768)
    const float* w      = (const float*)d_in[3];  // conv_w   (768,3,16,16)
    const float* bias   = (const float*)d_in[4];  // conv_b   (768)
    float* out = (float*)d_out;

    fused_kernel<<<N_PRODUCERS + BB, 256>>>(x, prompt, pkey, w, bias, out);
}